// round 5
// baseline (speedup 1.0000x reference)
#include <cuda_runtime.h>
#include <cuda_bf16.h>
#include <cstdint>

// Problem constants (VectorQuantizer_317827580710)
#define NB   32
#define D    256
#define HW   1024
#define N    32768
#define K    1024
#define QELEMS (N * D)
#define NPART  1024

#define TAU   3e-3f
#define CMAX  12

// Scratch (no device allocation allowed)
__device__ float g_wnorm[K];
__device__ float g_xnorm[N];
__device__ int   g_idx[N];
__device__ int   g_hist[K];
__device__ float g_partial[NPART];
__device__ int   g_cand[N * CMAX];
__device__ int   g_ncand[N];
__device__ __nv_bfloat16 g_xh[N * D];
__device__ float         g_xf[N * D];     // x transposed to [n][d] fp32
__device__ __nv_bfloat16 g_wh[K * D];

// ---------------- PTX helpers (base compute_103 compatible only) ----------
__device__ __forceinline__ uint32_t smem_u32(const void* p) {
    uint32_t a;
    asm("{ .reg .u64 t; cvta.to.shared.u64 t, %1; cvt.u32.u64 %0, t; }"
        : "=r"(a) : "l"(p));
    return a;
}
__device__ __forceinline__ void cpa16(uint32_t dst, const void* src) {
    asm volatile("cp.async.ca.shared.global [%0], [%1], 16;" :: "r"(dst), "l"(src));
}
__device__ __forceinline__ void ldsm4(uint32_t* r, uint32_t a) {
    asm volatile("ldmatrix.sync.aligned.m8n8.x4.shared.b16 {%0,%1,%2,%3}, [%4];"
                 : "=r"(r[0]), "=r"(r[1]), "=r"(r[2]), "=r"(r[3]) : "r"(a));
}
__device__ __forceinline__ void ldsm2(uint32_t* r, uint32_t a) {
    asm volatile("ldmatrix.sync.aligned.m8n8.x2.shared.b16 {%0,%1}, [%2];"
                 : "=r"(r[0]), "=r"(r[1]) : "r"(a));
}
__device__ __forceinline__ void mma16816(float* c, const uint32_t* a, const uint32_t* b) {
    asm volatile(
        "mma.sync.aligned.m16n8k16.row.col.f32.bf16.bf16.f32 "
        "{%0,%1,%2,%3}, {%4,%5,%6,%7}, {%8,%9}, {%0,%1,%2,%3};"
        : "+f"(c[0]), "+f"(c[1]), "+f"(c[2]), "+f"(c[3])
        : "r"(a[0]), "r"(a[1]), "r"(a[2]), "r"(a[3]), "r"(b[0]), "r"(b[1]));
}

__device__ __forceinline__ float block_reduce_f(float v, float* s) {
    int tid = threadIdx.x;
#pragma unroll
    for (int o = 16; o; o >>= 1) v += __shfl_down_sync(0xffffffffu, v, o);
    if ((tid & 31) == 0) s[tid >> 5] = v;
    __syncthreads();
    if (tid < 32) {
        v = (tid < 8) ? s[tid] : 0.f;
#pragma unroll
        for (int o = 4; o; o >>= 1) v += __shfl_down_sync(0xffffffffu, v, o);
    }
    return v;
}

// ---------------------------------------------------------------------------
// Kernel 0a: codebook squared norms (fp64 -> fp32) + hist zero.
__global__ __launch_bounds__(256) void k_wnorm(const float* __restrict__ w) {
    __shared__ double sd[8];
    int c = blockIdx.x, tid = threadIdx.x;
    float v = w[c * D + tid];
    double s = (double)v * (double)v;
#pragma unroll
    for (int o = 16; o; o >>= 1) s += __shfl_down_sync(0xffffffffu, s, o);
    if ((tid & 31) == 0) sd[tid >> 5] = s;
    __syncthreads();
    if (tid == 0) {
        double t = 0.0;
        for (int i = 0; i < 8; i++) t += sd[i];
        g_wnorm[c] = (float)t;
        g_hist[c] = 0;
    }
}

// Kernel 0b: per-row ||x||^2 (fp64 -> fp32).
__global__ __launch_bounds__(256) void k_xnorm(const float* __restrict__ x) {
    __shared__ double part[8][32];
    int tx = threadIdx.x, ty = threadIdx.y;
    int n0 = blockIdx.x * 32;
    int b  = n0 >> 10;
    int hw = (n0 & (HW - 1)) + tx;
    const float* xb = x + b * (D * HW) + hw;
    double s = 0.0;
    for (int d = ty; d < D; d += 8) {
        float v = xb[d * HW];
        s += (double)v * (double)v;
    }
    part[ty][tx] = s;
    __syncthreads();
    if (ty == 0) {
        double t = 0.0;
#pragma unroll
        for (int i = 0; i < 8; i++) t += part[i][tx];
        g_xnorm[n0 + tx] = (float)t;
    }
}

// Kernel 0c: codebook -> bf16.
__global__ __launch_bounds__(256) void k_cvtw(const float* __restrict__ w) {
    int i0 = (blockIdx.x * 256 + threadIdx.x) * 4;
#pragma unroll
    for (int j = 0; j < 4; j++) g_wh[i0 + j] = __float2bfloat16(w[i0 + j]);
}

// Kernel 0d: x -> [n][d] transpose; write fp32 + bf16.
// grid (HW/64, D/64, NB), block 256.
__global__ __launch_bounds__(256) void k_cvtx(const float* __restrict__ x) {
    __shared__ float t[64][65];
    int tid = threadIdx.x;
    int ht = blockIdx.x, dt = blockIdx.y, b = blockIdx.z;
    const float* xb = x + b * (D * HW) + dt * 64 * HW + ht * 64;
    int cr = tid >> 6, cc = tid & 63;
#pragma unroll
    for (int i = 0; i < 16; i++) {
        int d = i * 4 + cr;
        t[d][cc] = xb[d * HW + cc];
    }
    __syncthreads();
    int hwl = tid >> 2, dg = (tid & 3) * 16;
    long long base = (long long)(b * HW + ht * 64 + hwl) * D + dt * 64;
#pragma unroll
    for (int j = 0; j < 16; j++) {
        int d = dg + j;
        float v = t[d][hwl];
        g_xh[base + d] = __float2bfloat16(v);
        g_xf[base + d] = v;
    }
}

// ---------------------------------------------------------------------------
// Kernel 1: bf16 mma.sync approx distance GEMM + candidate selection.
// grid = N/128 = 256 CTAs, block 256 (8 warps).
// Dyn smem: A[128][528B pitch] | B[128][528B pitch] | C float[128][133].
#define A_OFF 0
#define B_OFF 67584
#define C_OFF 135168
#define KMMA_SMEM 203264

__global__ __launch_bounds__(256) void k_mma() {
    extern __shared__ char dsm[];
    const uint32_t smb = smem_u32(dsm);
    float* Cs = (float*)(dsm + C_OFF);

    const int tid = threadIdx.x, lane = tid & 31, wid = tid >> 5;
    const int wr = wid & 1, wc = wid >> 1;      // warp tile: rows 64*wr, cols 32*wc
    const int gid = lane >> 2, tig = lane & 3;
    const int n0 = blockIdx.x * 128;

    // ldmatrix per-lane base addresses (pitch 528 = 33*16B -> conflict-free)
    const uint32_t aL = smb + A_OFF + (64 * wr + (lane & 15)) * 528 + ((lane >> 4) << 4);
    const uint32_t bL = smb + B_OFF + (32 * wc + (lane & 7)) * 528 + (((lane >> 3) & 1) << 4);

    // Load resident A: 128 rows x 256 bf16 (512B payload, 528B pitch)
    for (int g = tid; g < 4096; g += 256) {
        int r = g >> 5, c = g & 31;
        cpa16(smb + A_OFF + r * 528 + c * 16, g_xh + (n0 + r) * D + c * 8);
    }
    asm volatile("cp.async.commit_group;");
    asm volatile("cp.async.wait_group 0;" ::: "memory");
    __syncthreads();

    float runmin = 3.4e38f;
    int   cnt = 0;

    float acc[4][4][4];
#pragma unroll
    for (int mi = 0; mi < 4; mi++)
#pragma unroll
        for (int nj = 0; nj < 4; nj++)
#pragma unroll
            for (int q = 0; q < 4; q++) acc[mi][nj][q] = 0.f;

    for (int ccn = 0; ccn < 8; ccn++) {
        // Load B chunk: 128 codes x 256 bf16
        for (int g = tid; g < 4096; g += 256) {
            int r = g >> 5, c = g & 31;
            cpa16(smb + B_OFF + r * 528 + c * 16, g_wh + (ccn * 128 + r) * D + c * 8);
        }
        asm volatile("cp.async.commit_group;");
        asm volatile("cp.async.wait_group 0;" ::: "memory");
        __syncthreads();   // B ready; also orders prior scan before C overwrite

        // Compute 128x128 distance dot tile
#pragma unroll 4
        for (int kt = 0; kt < 16; kt++) {
            uint32_t af[4][4], bf[4][2];
#pragma unroll
            for (int mi = 0; mi < 4; mi++) ldsm4(af[mi], aL + mi * (16 * 528) + kt * 32);
#pragma unroll
            for (int nj = 0; nj < 4; nj++) ldsm2(bf[nj], bL + nj * (8 * 528) + kt * 32);
#pragma unroll
            for (int mi = 0; mi < 4; mi++)
#pragma unroll
                for (int nj = 0; nj < 4; nj++) mma16816(acc[mi][nj], af[mi], bf[nj]);
        }

        // Stage C frags to smem (stride 133 -> conflict-free column scan)
#pragma unroll
        for (int mi = 0; mi < 4; mi++)
#pragma unroll
            for (int nj = 0; nj < 4; nj++) {
                int r0 = 64 * wr + 16 * mi + gid;
                int c0 = 32 * wc + 8 * nj + 2 * tig;
                Cs[r0 * 133 + c0]           = acc[mi][nj][0];
                Cs[r0 * 133 + c0 + 1]       = acc[mi][nj][1];
                Cs[(r0 + 8) * 133 + c0]     = acc[mi][nj][2];
                Cs[(r0 + 8) * 133 + c0 + 1] = acc[mi][nj][3];
                acc[mi][nj][0] = acc[mi][nj][1] = acc[mi][nj][2] = acc[mi][nj][3] = 0.f;
            }
        __syncthreads();

        // Scan: thread r folds row r (cols ascending keeps candidate order)
        if (tid < 128) {
            const int rg = n0 + tid;
            const float* cr = Cs + tid * 133;
#pragma unroll 4
            for (int c = 0; c < 128; c++) {
                float da = __ldg(&g_wnorm[ccn * 128 + c]) - 2.f * cr[c];
                if (da < runmin + TAU) {
                    if (cnt < CMAX) g_cand[rg * CMAX + cnt] = ccn * 128 + c;
                    cnt++;
                    if (da < runmin) runmin = da;
                }
            }
        }
        __syncthreads();
    }
    if (tid < 128) g_ncand[n0 + tid] = cnt;
}

// ---------------------------------------------------------------------------
// Kernel 2: exact re-verification. One warp per row, one lane per candidate.
// Reference-identical chain: acc = fmaf(x_k, w_k, acc) k-ascending;
// dist = (xn2 + wn2) - 2*acc; first-index tie-break.
__global__ __launch_bounds__(256) void k_exact(const float* __restrict__ w) {
    const int tid = threadIdx.x, wid = tid >> 5, lane = tid & 31;
    const int row = blockIdx.x * 8 + wid;
    const int nc = g_ncand[row];
    const float xs = g_xnorm[row];
    const float* xr = g_xf + (long long)row * D;

    float bestd = 3.4e38f;
    int   besti = 0x7fffffff;
    const int rounds = (nc <= CMAX) ? 1 : 32;    // overflow -> full scan
    for (int r = 0; r < rounds; r++) {
        int c = -1;
        if (nc <= CMAX) { if (lane < nc) c = g_cand[row * CMAX + lane]; }
        else            c = r * 32 + lane;
        if (c >= 0) {
            const float* wr = w + c * D;
            float acc = 0.f;
#pragma unroll 16
            for (int k = 0; k < D; k += 4) {
                float4 xv = *(const float4*)(xr + k);
                float4 wv = *(const float4*)(wr + k);
                acc = fmaf(xv.x, wv.x, acc);
                acc = fmaf(xv.y, wv.y, acc);
                acc = fmaf(xv.z, wv.z, acc);
                acc = fmaf(xv.w, wv.w, acc);
            }
            float t1 = xs + g_wnorm[c];
            float dist = t1 - 2.f * acc;
            if (dist < bestd || (dist == bestd && c < besti)) { bestd = dist; besti = c; }
        }
    }
#pragma unroll
    for (int o = 16; o; o >>= 1) {
        float od = __shfl_down_sync(0xffffffffu, bestd, o);
        int   oi = __shfl_down_sync(0xffffffffu, besti, o);
        if (od < bestd || (od == bestd && oi < besti)) { bestd = od; besti = oi; }
    }
    if (lane == 0) g_idx[row] = besti;
}

// ---------------------------------------------------------------------------
// Kernel 3: quantized_st = x + (q - x) in [B,C,H,W] layout + loss partials.
__global__ __launch_bounds__(256) void k_quant(const float* __restrict__ x,
                                               const float* __restrict__ w,
                                               float* __restrict__ outq) {
    __shared__ float4 Qs[32][64];
    __shared__ int sidx[32];
    __shared__ float sred[8];
    const int t = threadIdx.x;
    const int b = blockIdx.x >> 5;
    const int hw0 = (blockIdx.x & 31) << 5;
    if (t < 32) sidx[t] = g_idx[(b << 10) + hw0 + t];
    __syncthreads();

    const int r0 = t >> 6;
    const int c4 = t & 63;
#pragma unroll
    for (int j = 0; j < 8; ++j) {
        const int r = r0 + (j << 2);
        const float4* wr = (const float4*)(w + sidx[r] * D);
        Qs[r][c4 ^ r] = wr[c4];
    }
    __syncthreads();

    const int c = t & 31;
    const int s0 = t >> 5;
    const float* xb = x + b * (D * HW) + hw0 + c;
    float*       ob = outq + b * (D * HW) + hw0 + c;
    float accv = 0.f;
#pragma unroll
    for (int j = 0; j < 8; ++j) {
        const int s = s0 + (j << 3);
        float4 q = Qs[c][s ^ c];
        const int d = s << 2;
        float qq[4] = {q.x, q.y, q.z, q.w};
#pragma unroll
        for (int k2 = 0; k2 < 4; ++k2) {
            float xv = xb[(d + k2) * HW];
            float df = qq[k2] - xv;
            ob[(d + k2) * HW] = xv + df;
            accv += df * df;
        }
    }
    float v = block_reduce_f(accv, sred);
    if (t == 0) g_partial[blockIdx.x] = v;
}

// ---------------------------------------------------------------------------
// Kernel 4: one-hot encodings + exact int histogram.
__global__ __launch_bounds__(256) void k_enc(float2* __restrict__ enc) {
    unsigned gid = blockIdx.x * 256u + threadIdx.x;
    int n  = gid >> 9;
    int c2 = gid & 511;
    int idx = __ldg(&g_idx[n]);
    float2 v = make_float2(0.f, 0.f);
    if ((idx >> 1) == c2) {
        if (idx & 1) v.y = 1.f; else v.x = 1.f;
        atomicAdd(&g_hist[idx], 1);
    }
    enc[gid] = v;
}

// ---------------------------------------------------------------------------
// Kernel 5: finalize loss + perplexity.
__global__ __launch_bounds__(256) void k_final(float* __restrict__ out) {
    __shared__ double sd[8];
    int tid = threadIdx.x;

    double s = 0.0;
    for (int i = tid; i < NPART; i += 256) s += (double)g_partial[i];
#pragma unroll
    for (int o = 16; o; o >>= 1) s += __shfl_down_sync(0xffffffffu, s, o);
    if ((tid & 31) == 0) sd[tid >> 5] = s;
    __syncthreads();
    if (tid == 0) {
        double t = 0.0;
        for (int i = 0; i < 8; i++) t += sd[i];
        out[0] = (float)(t / (double)QELEMS * 1.25);
    }
    __syncthreads();

    double e = 0.0;
    for (int i = tid; i < K; i += 256) {
        double p = (double)g_hist[i] / (double)N;
        e += p * log(p + 1e-10);
    }
#pragma unroll
    for (int o = 16; o; o >>= 1) e += __shfl_down_sync(0xffffffffu, e, o);
    if ((tid & 31) == 0) sd[tid >> 5] = e;
    __syncthreads();
    if (tid == 0) {
        double t = 0.0;
        for (int i = 0; i < 8; i++) t += sd[i];
        out[1 + QELEMS] = (float)exp(-t);
    }
}

// ---------------------------------------------------------------------------
extern "C" void kernel_launch(void* const* d_in, const int* in_sizes, int n_in,
                              void* d_out, int out_size) {
    const float* x = (const float*)d_in[0];   // inputs [32,256,32,32]
    const float* w = (const float*)d_in[1];   // weight [1024,256]
    float* out = (float*)d_out;

    cudaFuncSetAttribute(k_mma, cudaFuncAttributeMaxDynamicSharedMemorySize, KMMA_SMEM);

    k_wnorm <<<K, 256>>>(w);
    k_xnorm <<<N / 32, dim3(32, 8)>>>(x);
    k_cvtw  <<<(K * D) / 1024, 256>>>(w);
    k_cvtx  <<<dim3(HW / 64, D / 64, NB), 256>>>(x);
    k_mma   <<<N / 128, 256, KMMA_SMEM>>>();
    k_exact <<<N / 8, 256>>>(w);
    k_quant <<<NPART, 256>>>(x, w, out + 1);
    k_enc   <<<(N * (K / 2)) / 256, 256>>>((float2*)(out + 2 + QELEMS));
    k_final <<<1, 256>>>(out);
}

// round 6
// speedup vs baseline: 4.5090x; 4.5090x over previous
#include <cuda_runtime.h>
#include <cuda_bf16.h>
#include <cstdint>

// Problem constants (VectorQuantizer_317827580710)
#define NB   32
#define D    256
#define HW   1024
#define N    32768
#define K    1024
#define QELEMS (N * D)
#define NPART  1024

#define TAU   3e-3f
#define CMAX  16

// Scratch (no device allocation allowed)
__device__ float g_wnorm[K];
__device__ float g_xnorm[N];
__device__ int   g_idx[N];
__device__ int   g_hist[K];
__device__ float g_partial[NPART];
__device__ int   g_cand[N * CMAX];
__device__ int   g_ncand[N];
__device__ __nv_bfloat16 g_xh[N * D];
__device__ float         g_xf[N * D];     // x transposed to [n][d] fp32
__device__ __nv_bfloat16 g_wh[K * D];

// ---------------- PTX helpers (base compute_103 compatible only) ----------
__device__ __forceinline__ uint32_t smem_u32(const void* p) {
    uint32_t a;
    asm("{ .reg .u64 t; cvta.to.shared.u64 t, %1; cvt.u32.u64 %0, t; }"
        : "=r"(a) : "l"(p));
    return a;
}
__device__ __forceinline__ void cpa16(uint32_t dst, const void* src) {
    asm volatile("cp.async.ca.shared.global [%0], [%1], 16;" :: "r"(dst), "l"(src));
}
__device__ __forceinline__ void ldsm4(uint32_t* r, uint32_t a) {
    asm volatile("ldmatrix.sync.aligned.m8n8.x4.shared.b16 {%0,%1,%2,%3}, [%4];"
                 : "=r"(r[0]), "=r"(r[1]), "=r"(r[2]), "=r"(r[3]) : "r"(a));
}
__device__ __forceinline__ void ldsm2(uint32_t* r, uint32_t a) {
    asm volatile("ldmatrix.sync.aligned.m8n8.x2.shared.b16 {%0,%1}, [%2];"
                 : "=r"(r[0]), "=r"(r[1]) : "r"(a));
}
__device__ __forceinline__ void mma16816(float* c, const uint32_t* a, const uint32_t* b) {
    asm volatile(
        "mma.sync.aligned.m16n8k16.row.col.f32.bf16.bf16.f32 "
        "{%0,%1,%2,%3}, {%4,%5,%6,%7}, {%8,%9}, {%0,%1,%2,%3};"
        : "+f"(c[0]), "+f"(c[1]), "+f"(c[2]), "+f"(c[3])
        : "r"(a[0]), "r"(a[1]), "r"(a[2]), "r"(a[3]), "r"(b[0]), "r"(b[1]));
}

__device__ __forceinline__ float block_reduce_f(float v, float* s) {
    int tid = threadIdx.x;
#pragma unroll
    for (int o = 16; o; o >>= 1) v += __shfl_down_sync(0xffffffffu, v, o);
    if ((tid & 31) == 0) s[tid >> 5] = v;
    __syncthreads();
    if (tid < 32) {
        v = (tid < 8) ? s[tid] : 0.f;
#pragma unroll
        for (int o = 4; o; o >>= 1) v += __shfl_down_sync(0xffffffffu, v, o);
    }
    return v;
}

// ---------------------------------------------------------------------------
// Kernel 0a: codebook squared norms (fp64 -> fp32) + hist zero.
__global__ __launch_bounds__(256) void k_wnorm(const float* __restrict__ w) {
    __shared__ double sd[8];
    int c = blockIdx.x, tid = threadIdx.x;
    float v = w[c * D + tid];
    double s = (double)v * (double)v;
#pragma unroll
    for (int o = 16; o; o >>= 1) s += __shfl_down_sync(0xffffffffu, s, o);
    if ((tid & 31) == 0) sd[tid >> 5] = s;
    __syncthreads();
    if (tid == 0) {
        double t = 0.0;
        for (int i = 0; i < 8; i++) t += sd[i];
        g_wnorm[c] = (float)t;
        g_hist[c] = 0;
    }
}

// Kernel 0b: per-row ||x||^2 (fp64 -> fp32).
__global__ __launch_bounds__(256) void k_xnorm(const float* __restrict__ x) {
    __shared__ double part[8][32];
    int tx = threadIdx.x, ty = threadIdx.y;
    int n0 = blockIdx.x * 32;
    int b  = n0 >> 10;
    int hw = (n0 & (HW - 1)) + tx;
    const float* xb = x + b * (D * HW) + hw;
    double s = 0.0;
    for (int d = ty; d < D; d += 8) {
        float v = xb[d * HW];
        s += (double)v * (double)v;
    }
    part[ty][tx] = s;
    __syncthreads();
    if (ty == 0) {
        double t = 0.0;
#pragma unroll
        for (int i = 0; i < 8; i++) t += part[i][tx];
        g_xnorm[n0 + tx] = (float)t;
    }
}

// Kernel 0c: codebook -> bf16.
__global__ __launch_bounds__(256) void k_cvtw(const float* __restrict__ w) {
    int i0 = (blockIdx.x * 256 + threadIdx.x) * 4;
#pragma unroll
    for (int j = 0; j < 4; j++) g_wh[i0 + j] = __float2bfloat16(w[i0 + j]);
}

// Kernel 0d: x -> [n][d] transpose; write fp32 + bf16.
// grid (HW/64, D/64, NB), block 256.
__global__ __launch_bounds__(256) void k_cvtx(const float* __restrict__ x) {
    __shared__ float t[64][65];
    int tid = threadIdx.x;
    int ht = blockIdx.x, dt = blockIdx.y, b = blockIdx.z;
    const float* xb = x + b * (D * HW) + dt * 64 * HW + ht * 64;
    int cr = tid >> 6, cc = tid & 63;
#pragma unroll
    for (int i = 0; i < 16; i++) {
        int d = i * 4 + cr;
        t[d][cc] = xb[d * HW + cc];
    }
    __syncthreads();
    int hwl = tid >> 2, dg = (tid & 3) * 16;
    long long base = (long long)(b * HW + ht * 64 + hwl) * D + dt * 64;
#pragma unroll
    for (int j = 0; j < 16; j++) {
        int d = dg + j;
        float v = t[d][hwl];
        g_xh[base + d] = __float2bfloat16(v);
        g_xf[base + d] = v;
    }
}

// ---------------------------------------------------------------------------
// Kernel 1: bf16 mma.sync approx distance GEMM + two-pass candidate selection.
// grid = N/128 = 256 CTAs, block 256 (8 warps).
// Dyn smem: A[128][528B pitch] | B[128][528B pitch] | C float[128][133].
#define A_OFF 0
#define B_OFF 67584
#define C_OFF 135168
#define KMMA_SMEM 203264

__global__ __launch_bounds__(256) void k_mma() {
    extern __shared__ char dsm[];
    const uint32_t smb = smem_u32(dsm);
    float* Cs = (float*)(dsm + C_OFF);

    const int tid = threadIdx.x, lane = tid & 31, wid = tid >> 5;
    const int wr = wid & 1, wc = wid >> 1;      // warp tile: rows 64*wr, cols 32*wc
    const int gid = lane >> 2, tig = lane & 3;
    const int n0 = blockIdx.x * 128;

    // ldmatrix per-lane base addresses (pitch 528 = 33*16B -> conflict-free)
    const uint32_t aL = smb + A_OFF + (64 * wr + (lane & 15)) * 528 + ((lane >> 4) << 4);
    const uint32_t bL = smb + B_OFF + (32 * wc + (lane & 7)) * 528 + (((lane >> 3) & 1) << 4);

    // Prologue: resident A (128 x 256 bf16) + B chunk 0
    for (int g = tid; g < 4096; g += 256) {
        int r = g >> 5, c = g & 31;
        cpa16(smb + A_OFF + r * 528 + c * 16, g_xh + (n0 + r) * D + c * 8);
        cpa16(smb + B_OFF + r * 528 + c * 16, g_wh + r * D + c * 8);
    }
    asm volatile("cp.async.commit_group;");
    asm volatile("cp.async.wait_group 0;" ::: "memory");
    __syncthreads();

    float runmin = 3.4e38f;
    int   cnt = 0;

    float acc[4][4][4];
#pragma unroll
    for (int mi = 0; mi < 4; mi++)
#pragma unroll
        for (int nj = 0; nj < 4; nj++)
#pragma unroll
            for (int q = 0; q < 4; q++) acc[mi][nj][q] = 0.f;

    for (int ccn = 0; ccn < 8; ccn++) {
        // Compute 128x128 dot tile from resident A and current B
#pragma unroll 4
        for (int kt = 0; kt < 16; kt++) {
            uint32_t af[4][4], bf[4][2];
#pragma unroll
            for (int mi = 0; mi < 4; mi++) ldsm4(af[mi], aL + mi * (16 * 528) + kt * 32);
#pragma unroll
            for (int nj = 0; nj < 4; nj++) ldsm2(bf[nj], bL + nj * (8 * 528) + kt * 32);
#pragma unroll
            for (int mi = 0; mi < 4; mi++)
#pragma unroll
                for (int nj = 0; nj < 4; nj++) mma16816(acc[mi][nj], af[mi], bf[nj]);
        }

        // Stage da = wnorm - 2*dot into Cs (stride 133 -> conflict-free scan)
#pragma unroll
        for (int nj = 0; nj < 4; nj++) {
            const int c0 = 32 * wc + 8 * nj + 2 * tig;
            const float wn0 = __ldg(&g_wnorm[ccn * 128 + c0]);
            const float wn1 = __ldg(&g_wnorm[ccn * 128 + c0 + 1]);
#pragma unroll
            for (int mi = 0; mi < 4; mi++) {
                int r0 = 64 * wr + 16 * mi + gid;
                Cs[r0 * 133 + c0]           = wn0 - 2.f * acc[mi][nj][0];
                Cs[r0 * 133 + c0 + 1]       = wn1 - 2.f * acc[mi][nj][1];
                Cs[(r0 + 8) * 133 + c0]     = wn0 - 2.f * acc[mi][nj][2];
                Cs[(r0 + 8) * 133 + c0 + 1] = wn1 - 2.f * acc[mi][nj][3];
                acc[mi][nj][0] = acc[mi][nj][1] = acc[mi][nj][2] = acc[mi][nj][3] = 0.f;
            }
        }
        __syncthreads();   // compute done (B free), Cs ready

        // Prefetch next B chunk; overlaps with the scan below
        if (ccn < 7) {
            for (int g = tid; g < 4096; g += 256) {
                int r = g >> 5, c = g & 31;
                cpa16(smb + B_OFF + r * 528 + c * 16,
                      g_wh + ((ccn + 1) * 128 + r) * D + c * 8);
            }
            asm volatile("cp.async.commit_group;");
        }

        // Two-pass scan: (1) chunk min -> runmin, (2) append within TAU
        if (tid < 128) {
            const int rg = n0 + tid;
            const float* cr = Cs + tid * 133;
            float m = cr[0];
#pragma unroll 8
            for (int c = 1; c < 128; c++) m = fminf(m, cr[c]);
            if (m < runmin) runmin = m;
            const float thr = runmin + TAU;
#pragma unroll 4
            for (int c = 0; c < 128; c++) {
                if (cr[c] < thr) {
                    if (cnt < CMAX) g_cand[rg * CMAX + cnt] = ccn * 128 + c;
                    cnt++;
                }
            }
        }
        if (ccn < 7) asm volatile("cp.async.wait_group 0;" ::: "memory");
        __syncthreads();   // B ready; Cs scan done before overwrite
    }
    if (tid < 128) g_ncand[n0 + tid] = cnt;
}

// ---------------------------------------------------------------------------
// Kernel 2: exact re-verification. One warp per row, one lane per candidate.
// Reference-identical chain: acc = fmaf(x_k, w_k, acc) k-ascending;
// dist = (xn2 + wn2) - 2*acc; first-index tie-break.
__global__ __launch_bounds__(256) void k_exact(const float* __restrict__ w) {
    const int tid = threadIdx.x, wid = tid >> 5, lane = tid & 31;
    const int row = blockIdx.x * 8 + wid;
    const int nc = g_ncand[row];
    const float xs = g_xnorm[row];
    const float* xr = g_xf + (long long)row * D;

    float bestd = 3.4e38f;
    int   besti = 0x7fffffff;
    const int rounds = (nc <= CMAX) ? 1 : 32;    // overflow -> full scan (rare)
    for (int r = 0; r < rounds; r++) {
        int c = -1;
        if (nc <= CMAX) { if (lane < nc) c = g_cand[row * CMAX + lane]; }
        else            c = r * 32 + lane;
        if (c >= 0) {
            const float* wr = w + c * D;
            float acc = 0.f;
#pragma unroll 16
            for (int k = 0; k < D; k += 4) {
                float4 xv = *(const float4*)(xr + k);
                float4 wv = *(const float4*)(wr + k);
                acc = fmaf(xv.x, wv.x, acc);
                acc = fmaf(xv.y, wv.y, acc);
                acc = fmaf(xv.z, wv.z, acc);
                acc = fmaf(xv.w, wv.w, acc);
            }
            float t1 = xs + g_wnorm[c];
            float dist = t1 - 2.f * acc;
            if (dist < bestd || (dist == bestd && c < besti)) { bestd = dist; besti = c; }
        }
    }
#pragma unroll
    for (int o = 16; o; o >>= 1) {
        float od = __shfl_down_sync(0xffffffffu, bestd, o);
        int   oi = __shfl_down_sync(0xffffffffu, besti, o);
        if (od < bestd || (od == bestd && oi < besti)) { bestd = od; besti = oi; }
    }
    if (lane == 0) g_idx[row] = besti;
}

// ---------------------------------------------------------------------------
// Kernel 3: quantized_st = x + (q - x) in [B,C,H,W] layout + loss partials.
__global__ __launch_bounds__(256) void k_quant(const float* __restrict__ x,
                                               const float* __restrict__ w,
                                               float* __restrict__ outq) {
    __shared__ float4 Qs[32][64];
    __shared__ int sidx[32];
    __shared__ float sred[8];
    const int t = threadIdx.x;
    const int b = blockIdx.x >> 5;
    const int hw0 = (blockIdx.x & 31) << 5;
    if (t < 32) sidx[t] = g_idx[(b << 10) + hw0 + t];
    __syncthreads();

    const int r0 = t >> 6;
    const int c4 = t & 63;
#pragma unroll
    for (int j = 0; j < 8; ++j) {
        const int r = r0 + (j << 2);
        const float4* wr = (const float4*)(w + sidx[r] * D);
        Qs[r][c4 ^ r] = wr[c4];
    }
    __syncthreads();

    const int c = t & 31;
    const int s0 = t >> 5;
    const float* xb = x + b * (D * HW) + hw0 + c;
    float*       ob = outq + b * (D * HW) + hw0 + c;
    float accv = 0.f;
#pragma unroll
    for (int j = 0; j < 8; ++j) {
        const int s = s0 + (j << 3);
        float4 q = Qs[c][s ^ c];
        const int d = s << 2;
        float qq[4] = {q.x, q.y, q.z, q.w};
#pragma unroll
        for (int k2 = 0; k2 < 4; ++k2) {
            float xv = xb[(d + k2) * HW];
            float df = qq[k2] - xv;
            ob[(d + k2) * HW] = xv + df;
            accv += df * df;
        }
    }
    float v = block_reduce_f(accv, sred);
    if (t == 0) g_partial[blockIdx.x] = v;
}

// ---------------------------------------------------------------------------
// Kernel 4: one-hot encodings + exact int histogram.
__global__ __launch_bounds__(256) void k_enc(float2* __restrict__ enc) {
    unsigned gid = blockIdx.x * 256u + threadIdx.x;
    int n  = gid >> 9;
    int c2 = gid & 511;
    int idx = __ldg(&g_idx[n]);
    float2 v = make_float2(0.f, 0.f);
    if ((idx >> 1) == c2) {
        if (idx & 1) v.y = 1.f; else v.x = 1.f;
        atomicAdd(&g_hist[idx], 1);
    }
    enc[gid] = v;
}

// ---------------------------------------------------------------------------
// Kernel 5: finalize loss + perplexity.
__global__ __launch_bounds__(256) void k_final(float* __restrict__ out) {
    __shared__ double sd[8];
    int tid = threadIdx.x;

    double s = 0.0;
    for (int i = tid; i < NPART; i += 256) s += (double)g_partial[i];
#pragma unroll
    for (int o = 16; o; o >>= 1) s += __shfl_down_sync(0xffffffffu, s, o);
    if ((tid & 31) == 0) sd[tid >> 5] = s;
    __syncthreads();
    if (tid == 0) {
        double t = 0.0;
        for (int i = 0; i < 8; i++) t += sd[i];
        out[0] = (float)(t / (double)QELEMS * 1.25);
    }
    __syncthreads();

    double e = 0.0;
    for (int i = tid; i < K; i += 256) {
        double p = (double)g_hist[i] / (double)N;
        e += p * log(p + 1e-10);
    }
#pragma unroll
    for (int o = 16; o; o >>= 1) e += __shfl_down_sync(0xffffffffu, e, o);
    if ((tid & 31) == 0) sd[tid >> 5] = e;
    __syncthreads();
    if (tid == 0) {
        double t = 0.0;
        for (int i = 0; i < 8; i++) t += sd[i];
        out[1 + QELEMS] = (float)exp(-t);
    }
}

// ---------------------------------------------------------------------------
extern "C" void kernel_launch(void* const* d_in, const int* in_sizes, int n_in,
                              void* d_out, int out_size) {
    const float* x = (const float*)d_in[0];   // inputs [32,256,32,32]
    const float* w = (const float*)d_in[1];   // weight [1024,256]
    float* out = (float*)d_out;

    cudaFuncSetAttribute(k_mma, cudaFuncAttributeMaxDynamicSharedMemorySize, KMMA_SMEM);

    k_wnorm <<<K, 256>>>(w);
    k_xnorm <<<N / 32, dim3(32, 8)>>>(x);
    k_cvtw  <<<(K * D) / 1024, 256>>>(w);
    k_cvtx  <<<dim3(HW / 64, D / 64, NB), 256>>>(x);
    k_mma   <<<N / 128, 256, KMMA_SMEM>>>();
    k_exact <<<N / 8, 256>>>(w);
    k_quant <<<NPART, 256>>>(x, w, out + 1);
    k_enc   <<<(N * (K / 2)) / 256, 256>>>((float2*)(out + 2 + QELEMS));
    k_final <<<1, 256>>>(out);
}

// round 7
// speedup vs baseline: 5.3950x; 1.1965x over previous
#include <cuda_runtime.h>
#include <cuda_bf16.h>
#include <cstdint>

// Problem constants (VectorQuantizer_317827580710)
#define NB   32
#define D    256
#define HW   1024
#define N    32768
#define K    1024
#define QELEMS (N * D)
#define NPART  1024

#define TAU   3e-3f
#define CMAX  16

// Scratch (no device allocation allowed)
__device__ float g_wnorm[K];
__device__ float g_xnorm[N];
__device__ int   g_idx[N];
__device__ int   g_hist[K];
__device__ float g_partial[NPART];
__device__ int   g_cand[N * CMAX];
__device__ int   g_ncand[N];
__device__ __align__(16) __nv_bfloat16 g_xh[N * D];
__device__ __align__(16) float         g_xf[N * D];   // x transposed [n][d] fp32
__device__ __align__(16) __nv_bfloat16 g_wh[K * D];

// ---------------- PTX helpers (base compute_103 compatible only) ----------
__device__ __forceinline__ uint32_t smem_u32(const void* p) {
    uint32_t a;
    asm("{ .reg .u64 t; cvta.to.shared.u64 t, %1; cvt.u32.u64 %0, t; }"
        : "=r"(a) : "l"(p));
    return a;
}
__device__ __forceinline__ void cpa16(uint32_t dst, const void* src) {
    asm volatile("cp.async.ca.shared.global [%0], [%1], 16;" :: "r"(dst), "l"(src));
}
__device__ __forceinline__ void ldsm4(uint32_t* r, uint32_t a) {
    asm volatile("ldmatrix.sync.aligned.m8n8.x4.shared.b16 {%0,%1,%2,%3}, [%4];"
                 : "=r"(r[0]), "=r"(r[1]), "=r"(r[2]), "=r"(r[3]) : "r"(a));
}
__device__ __forceinline__ void ldsm2(uint32_t* r, uint32_t a) {
    asm volatile("ldmatrix.sync.aligned.m8n8.x2.shared.b16 {%0,%1}, [%2];"
                 : "=r"(r[0]), "=r"(r[1]) : "r"(a));
}
__device__ __forceinline__ void mma16816(float* c, const uint32_t* a, const uint32_t* b) {
    asm volatile(
        "mma.sync.aligned.m16n8k16.row.col.f32.bf16.bf16.f32 "
        "{%0,%1,%2,%3}, {%4,%5,%6,%7}, {%8,%9}, {%0,%1,%2,%3};"
        : "+f"(c[0]), "+f"(c[1]), "+f"(c[2]), "+f"(c[3])
        : "r"(a[0]), "r"(a[1]), "r"(a[2]), "r"(a[3]), "r"(b[0]), "r"(b[1]));
}

__device__ __forceinline__ float block_reduce_f(float v, float* s) {
    int tid = threadIdx.x;
#pragma unroll
    for (int o = 16; o; o >>= 1) v += __shfl_down_sync(0xffffffffu, v, o);
    if ((tid & 31) == 0) s[tid >> 5] = v;
    __syncthreads();
    if (tid < 32) {
        v = (tid < 8) ? s[tid] : 0.f;
#pragma unroll
        for (int o = 4; o; o >>= 1) v += __shfl_down_sync(0xffffffffu, v, o);
    }
    return v;
}

// ---------------------------------------------------------------------------
// Kernel 0a: codebook squared norms (fp64 -> fp32) + hist zero.
__global__ __launch_bounds__(256) void k_wnorm(const float* __restrict__ w) {
    __shared__ double sd[8];
    int c = blockIdx.x, tid = threadIdx.x;
    float v = w[c * D + tid];
    double s = (double)v * (double)v;
#pragma unroll
    for (int o = 16; o; o >>= 1) s += __shfl_down_sync(0xffffffffu, s, o);
    if ((tid & 31) == 0) sd[tid >> 5] = s;
    __syncthreads();
    if (tid == 0) {
        double t = 0.0;
        for (int i = 0; i < 8; i++) t += sd[i];
        g_wnorm[c] = (float)t;
        g_hist[c] = 0;
    }
}

// Kernel 0b: per-row ||x||^2 (fp64 -> fp32).
__global__ __launch_bounds__(256) void k_xnorm(const float* __restrict__ x) {
    __shared__ double part[8][32];
    int tx = threadIdx.x, ty = threadIdx.y;
    int n0 = blockIdx.x * 32;
    int b  = n0 >> 10;
    int hw = (n0 & (HW - 1)) + tx;
    const float* xb = x + b * (D * HW) + hw;
    double s = 0.0;
    for (int d = ty; d < D; d += 8) {
        float v = xb[d * HW];
        s += (double)v * (double)v;
    }
    part[ty][tx] = s;
    __syncthreads();
    if (ty == 0) {
        double t = 0.0;
#pragma unroll
        for (int i = 0; i < 8; i++) t += part[i][tx];
        g_xnorm[n0 + tx] = (float)t;
    }
}

// Kernel 0c: codebook -> bf16.
__global__ __launch_bounds__(256) void k_cvtw(const float* __restrict__ w) {
    int i0 = (blockIdx.x * 256 + threadIdx.x) * 4;
#pragma unroll
    for (int j = 0; j < 4; j++) g_wh[i0 + j] = __float2bfloat16(w[i0 + j]);
}

// Kernel 0d: x -> [n][d]; vectorized stores (float4 / uint4-of-bf16).
// grid (HW/32, NB), block 256. Smem XOR-swizzled: conflict-free both phases.
__global__ __launch_bounds__(256) void k_cvtx(const float* __restrict__ x) {
    __shared__ float t[256 * 32];   // t[d*32 + (hw ^ (d&31))]
    const int tid = threadIdx.x, lane = tid & 31, dg = tid >> 5;
    const int b = blockIdx.y, hwt = blockIdx.x;
    const float* xb = x + b * (D * HW) + hwt * 32;
#pragma unroll 8
    for (int i = 0; i < 32; i++) {
        int d = dg * 32 + i;
        t[d * 32 + (lane ^ (d & 31))] = xb[d * HW + lane];
    }
    __syncthreads();
    const int r = tid >> 3, kq = tid & 7;
    const long long n = (long long)b * HW + hwt * 32 + r;
    float* xf = g_xf + n * D;
    __nv_bfloat16* xh = g_xh + n * D;
#pragma unroll
    for (int j = 0; j < 4; j++) {
        int d0 = 8 * kq + 64 * j;
        float4 v0, v1;
        v0.x = t[(d0+0)*32 + (r ^ ((d0+0)&31))];
        v0.y = t[(d0+1)*32 + (r ^ ((d0+1)&31))];
        v0.z = t[(d0+2)*32 + (r ^ ((d0+2)&31))];
        v0.w = t[(d0+3)*32 + (r ^ ((d0+3)&31))];
        v1.x = t[(d0+4)*32 + (r ^ ((d0+4)&31))];
        v1.y = t[(d0+5)*32 + (r ^ ((d0+5)&31))];
        v1.z = t[(d0+6)*32 + (r ^ ((d0+6)&31))];
        v1.w = t[(d0+7)*32 + (r ^ ((d0+7)&31))];
        *(float4*)(xf + d0)     = v0;
        *(float4*)(xf + d0 + 4) = v1;
        __nv_bfloat162 p0 = __floats2bfloat162_rn(v0.x, v0.y);
        __nv_bfloat162 p1 = __floats2bfloat162_rn(v0.z, v0.w);
        __nv_bfloat162 p2 = __floats2bfloat162_rn(v1.x, v1.y);
        __nv_bfloat162 p3 = __floats2bfloat162_rn(v1.z, v1.w);
        uint4 u;
        u.x = *(uint32_t*)&p0; u.y = *(uint32_t*)&p1;
        u.z = *(uint32_t*)&p2; u.w = *(uint32_t*)&p3;
        *(uint4*)(xh + d0) = u;
    }
}

// ---------------------------------------------------------------------------
// Kernel 1: bf16 mma.sync approx distance GEMM + two-pass candidate selection.
// grid = N/128 = 256 CTAs, block 256 (8 warps). Smem 96KB -> 2 CTAs/SM, 1 wave.
// A resident 128x256 bf16 (512B pitch, XOR swizzle); B = 64-code chunks.
// Distances stay in registers; rowmin via shfl + smem; appends via smem atomics
// (order-free: k_exact tie-breaks by (dist, index)).
#define A_OFF 0
#define B_OFF 65536
#define KMMA_SMEM 98304

__global__ __launch_bounds__(256) void k_mma() {
    extern __shared__ char dsm[];
    __shared__ float rowmin_s[2][128];
    __shared__ float runmin_s[128];
    __shared__ int   cnt_s[128];

    const uint32_t smb = smem_u32(dsm);
    const int tid = threadIdx.x, lane = tid & 31, wid = tid >> 5;
    const int wr = wid & 3, wc = wid >> 2;     // rows 32*wr..+31, cols 32*wc..+31
    const int gid = lane >> 2, tig = lane & 3;
    const int n0 = blockIdx.x * 128;

    // ldmatrix lane addressing (XOR swizzle chunk^(row&7))
    const int arow = 32 * wr + (lane & 15);
    const uint32_t aRowBase = smb + A_OFF + arow * 512;
    const int ar7 = arow & 7, ach = lane >> 4;
    const int brow = 32 * wc + (lane & 7);
    const uint32_t bRowBase = smb + B_OFF + brow * 512;
    const int br7 = brow & 7, bch = (lane >> 3) & 1;

    // Prologue: resident A + B chunk 0
    for (int g = tid; g < 4096; g += 256) {
        int r = g >> 5, c = g & 31;
        cpa16(smb + A_OFF + r * 512 + ((c ^ (r & 7)) << 4), g_xh + (n0 + r) * D + c * 8);
    }
    for (int g = tid; g < 2048; g += 256) {
        int r = g >> 5, c = g & 31;
        cpa16(smb + B_OFF + r * 512 + ((c ^ (r & 7)) << 4), g_wh + r * D + c * 8);
    }
    asm volatile("cp.async.commit_group;");
    if (tid < 128) { runmin_s[tid] = 3.4e38f; cnt_s[tid] = 0; }
    asm volatile("cp.async.wait_group 0;" ::: "memory");
    __syncthreads();

    for (int cc = 0; cc < 16; cc++) {
        float acc[2][4][4];
#pragma unroll
        for (int mi = 0; mi < 2; mi++)
#pragma unroll
            for (int nj = 0; nj < 4; nj++)
#pragma unroll
                for (int q = 0; q < 4; q++) acc[mi][nj][q] = 0.f;

        // 128x64 dot tile
#pragma unroll 4
        for (int kt = 0; kt < 16; kt++) {
            uint32_t af[2][4], bf[4][2];
            const int ac = ((2 * kt + ach) ^ ar7) << 4;
            ldsm4(af[0], aRowBase + ac);
            ldsm4(af[1], aRowBase + 8192 + ac);
            const int bc = ((2 * kt + bch) ^ br7) << 4;
            ldsm2(bf[0], bRowBase + bc);
            ldsm2(bf[1], bRowBase + 4096 + bc);
            ldsm2(bf[2], bRowBase + 8192 + bc);
            ldsm2(bf[3], bRowBase + 12288 + bc);
#pragma unroll
            for (int mi = 0; mi < 2; mi++)
#pragma unroll
                for (int nj = 0; nj < 4; nj++) mma16816(acc[mi][nj], af[mi], bf[nj]);
        }

        // da = wnorm - 2*dot (in place) + per-thread row mins
#pragma unroll
        for (int nj = 0; nj < 4; nj++) {
            const int c0 = cc * 64 + 32 * wc + 8 * nj + 2 * tig;
            const float wn0 = __ldg(&g_wnorm[c0]);
            const float wn1 = __ldg(&g_wnorm[c0 + 1]);
#pragma unroll
            for (int mi = 0; mi < 2; mi++) {
                acc[mi][nj][0] = wn0 - 2.f * acc[mi][nj][0];
                acc[mi][nj][1] = wn1 - 2.f * acc[mi][nj][1];
                acc[mi][nj][2] = wn0 - 2.f * acc[mi][nj][2];
                acc[mi][nj][3] = wn1 - 2.f * acc[mi][nj][3];
            }
        }
        float rmin[2][2];
#pragma unroll
        for (int mi = 0; mi < 2; mi++) {
            rmin[mi][0] = fminf(fminf(acc[mi][0][0], acc[mi][0][1]),
                                fminf(acc[mi][1][0], acc[mi][1][1]));
            rmin[mi][0] = fminf(rmin[mi][0],
                          fminf(fminf(acc[mi][2][0], acc[mi][2][1]),
                                fminf(acc[mi][3][0], acc[mi][3][1])));
            rmin[mi][1] = fminf(fminf(acc[mi][0][2], acc[mi][0][3]),
                                fminf(acc[mi][1][2], acc[mi][1][3]));
            rmin[mi][1] = fminf(rmin[mi][1],
                          fminf(fminf(acc[mi][2][2], acc[mi][2][3]),
                                fminf(acc[mi][3][2], acc[mi][3][3])));
#pragma unroll
            for (int o = 1; o <= 2; o <<= 1) {
                rmin[mi][0] = fminf(rmin[mi][0], __shfl_xor_sync(0xffffffffu, rmin[mi][0], o));
                rmin[mi][1] = fminf(rmin[mi][1], __shfl_xor_sync(0xffffffffu, rmin[mi][1], o));
            }
            if (tig == 0) {
                rowmin_s[wc][32 * wr + 16 * mi + gid]     = rmin[mi][0];
                rowmin_s[wc][32 * wr + 16 * mi + gid + 8] = rmin[mi][1];
            }
        }
        __syncthreads();   // all MMA reads of B done; rowmin_s ready

        // Prefetch next B chunk (overlaps runmin update + appends)
        if (cc < 15) {
            for (int g = tid; g < 2048; g += 256) {
                int r = g >> 5, c = g & 31;
                cpa16(smb + B_OFF + r * 512 + ((c ^ (r & 7)) << 4),
                      g_wh + ((cc + 1) * 64 + r) * D + c * 8);
            }
            asm volatile("cp.async.commit_group;");
        }

        if (tid < 128) {
            float m = fminf(rowmin_s[0][tid], rowmin_s[1][tid]);
            if (m < runmin_s[tid]) runmin_s[tid] = m;
        }
        __syncthreads();

        // Append pass (two-pass: runmin already includes this chunk)
#pragma unroll
        for (int mi = 0; mi < 2; mi++)
#pragma unroll
            for (int h = 0; h < 2; h++) {
                const int row = 32 * wr + 16 * mi + gid + 8 * h;
                const float thr = runmin_s[row] + TAU;
#pragma unroll
                for (int nj = 0; nj < 4; nj++)
#pragma unroll
                    for (int q = 0; q < 2; q++) {
                        float v = acc[mi][nj][2 * h + q];
                        if (v < thr) {
                            int s = atomicAdd(&cnt_s[row], 1);
                            if (s < CMAX)
                                g_cand[(n0 + row) * CMAX + s] =
                                    cc * 64 + 32 * wc + 8 * nj + 2 * tig + q;
                        }
                    }
            }
        if (cc < 15) asm volatile("cp.async.wait_group 0;" ::: "memory");
        __syncthreads();
    }
    if (tid < 128) g_ncand[n0 + tid] = cnt_s[tid];
}

// ---------------------------------------------------------------------------
// Kernel 2: exact re-verification. One warp per row, one lane per candidate.
// Reference-identical chain: acc = fmaf(x_k, w_k, acc) k-ascending;
// dist = (xn2 + wn2) - 2*acc; (dist, index) lex-min -> first-index tie-break.
__global__ __launch_bounds__(256) void k_exact(const float* __restrict__ w) {
    const int tid = threadIdx.x, wid = tid >> 5, lane = tid & 31;
    const int row = blockIdx.x * 8 + wid;
    const int nc = g_ncand[row];
    const float xs = g_xnorm[row];
    const float* xr = g_xf + (long long)row * D;

    float bestd = 3.4e38f;
    int   besti = 0x7fffffff;
    const int rounds = (nc <= CMAX) ? 1 : 32;    // overflow -> full scan (rare)
    for (int r = 0; r < rounds; r++) {
        int c = -1;
        if (nc <= CMAX) { if (lane < nc) c = g_cand[row * CMAX + lane]; }
        else            c = r * 32 + lane;
        if (c >= 0) {
            const float* wr = w + c * D;
            float acc = 0.f;
#pragma unroll 16
            for (int k = 0; k < D; k += 4) {
                float4 xv = *(const float4*)(xr + k);
                float4 wv = *(const float4*)(wr + k);
                acc = fmaf(xv.x, wv.x, acc);
                acc = fmaf(xv.y, wv.y, acc);
                acc = fmaf(xv.z, wv.z, acc);
                acc = fmaf(xv.w, wv.w, acc);
            }
            float t1 = xs + g_wnorm[c];
            float dist = t1 - 2.f * acc;
            if (dist < bestd || (dist == bestd && c < besti)) { bestd = dist; besti = c; }
        }
    }
#pragma unroll
    for (int o = 16; o; o >>= 1) {
        float od = __shfl_down_sync(0xffffffffu, bestd, o);
        int   oi = __shfl_down_sync(0xffffffffu, besti, o);
        if (od < bestd || (od == bestd && oi < besti)) { bestd = od; besti = oi; }
    }
    if (lane == 0) g_idx[row] = besti;
}

// ---------------------------------------------------------------------------
// Kernel 3: quantized_st = x + (q - x) in [B,C,H,W] layout + loss partials.
__global__ __launch_bounds__(256) void k_quant(const float* __restrict__ x,
                                               const float* __restrict__ w,
                                               float* __restrict__ outq) {
    __shared__ float4 Qs[32][64];
    __shared__ int sidx[32];
    __shared__ float sred[8];
    const int t = threadIdx.x;
    const int b = blockIdx.x >> 5;
    const int hw0 = (blockIdx.x & 31) << 5;
    if (t < 32) sidx[t] = g_idx[(b << 10) + hw0 + t];
    __syncthreads();

    const int r0 = t >> 6;
    const int c4 = t & 63;
#pragma unroll
    for (int j = 0; j < 8; ++j) {
        const int r = r0 + (j << 2);
        const float4* wr = (const float4*)(w + sidx[r] * D);
        Qs[r][c4 ^ r] = wr[c4];
    }
    __syncthreads();

    const int c = t & 31;
    const int s0 = t >> 5;
    const float* xb = x + b * (D * HW) + hw0 + c;
    float*       ob = outq + b * (D * HW) + hw0 + c;
    float accv = 0.f;
#pragma unroll
    for (int j = 0; j < 8; ++j) {
        const int s = s0 + (j << 3);
        float4 q = Qs[c][s ^ c];
        const int d = s << 2;
        float qq[4] = {q.x, q.y, q.z, q.w};
#pragma unroll
        for (int k2 = 0; k2 < 4; ++k2) {
            float xv = xb[(d + k2) * HW];
            float df = qq[k2] - xv;
            ob[(d + k2) * HW] = xv + df;
            accv += df * df;
        }
    }
    float v = block_reduce_f(accv, sred);
    if (t == 0) g_partial[blockIdx.x] = v;
}

// ---------------------------------------------------------------------------
// Kernel 4: one-hot encodings + exact int histogram.
__global__ __launch_bounds__(256) void k_enc(float2* __restrict__ enc) {
    unsigned gid = blockIdx.x * 256u + threadIdx.x;
    int n  = gid >> 9;
    int c2 = gid & 511;
    int idx = __ldg(&g_idx[n]);
    float2 v = make_float2(0.f, 0.f);
    if ((idx >> 1) == c2) {
        if (idx & 1) v.y = 1.f; else v.x = 1.f;
        atomicAdd(&g_hist[idx], 1);
    }
    enc[gid] = v;
}

// ---------------------------------------------------------------------------
// Kernel 5: finalize loss + perplexity.
__global__ __launch_bounds__(256) void k_final(float* __restrict__ out) {
    __shared__ double sd[8];
    int tid = threadIdx.x;

    double s = 0.0;
    for (int i = tid; i < NPART; i += 256) s += (double)g_partial[i];
#pragma unroll
    for (int o = 16; o; o >>= 1) s += __shfl_down_sync(0xffffffffu, s, o);
    if ((tid & 31) == 0) sd[tid >> 5] = s;
    __syncthreads();
    if (tid == 0) {
        double t = 0.0;
        for (int i = 0; i < 8; i++) t += sd[i];
        out[0] = (float)(t / (double)QELEMS * 1.25);
    }
    __syncthreads();

    double e = 0.0;
    for (int i = tid; i < K; i += 256) {
        double p = (double)g_hist[i] / (double)N;
        e += p * log(p + 1e-10);
    }
#pragma unroll
    for (int o = 16; o; o >>= 1) e += __shfl_down_sync(0xffffffffu, e, o);
    if ((tid & 31) == 0) sd[tid >> 5] = e;
    __syncthreads();
    if (tid == 0) {
        double t = 0.0;
        for (int i = 0; i < 8; i++) t += sd[i];
        out[1 + QELEMS] = (float)exp(-t);
    }
}

// ---------------------------------------------------------------------------
extern "C" void kernel_launch(void* const* d_in, const int* in_sizes, int n_in,
                              void* d_out, int out_size) {
    const float* x = (const float*)d_in[0];   // inputs [32,256,32,32]
    const float* w = (const float*)d_in[1];   // weight [1024,256]
    float* out = (float*)d_out;

    cudaFuncSetAttribute(k_mma, cudaFuncAttributeMaxDynamicSharedMemorySize, KMMA_SMEM);

    // Order chosen so the profiler's fixed capture slot lands on k_mma.
    k_wnorm <<<K, 256>>>(w);
    k_cvtw  <<<(K * D) / 1024, 256>>>(w);
    k_cvtx  <<<dim3(HW / 32, NB), 256>>>(x);
    k_mma   <<<N / 128, 256, KMMA_SMEM>>>();
    k_xnorm <<<N / 32, dim3(32, 8)>>>(x);
    k_exact <<<N / 8, 256>>>(w);
    k_quant <<<NPART, 256>>>(x, w, out + 1);
    k_enc   <<<(N * (K / 2)) / 256, 256>>>((float2*)(out + 2 + QELEMS));
    k_final <<<1, 256>>>(out);
}